// round 1
// baseline (speedup 1.0000x reference)
#include <cuda_runtime.h>
#include <cuda_bf16.h>

// Problem constants
#define BB 4
#define SS 2048
#define DD 1024   // D_IN == D_H == DEPTH == 1024
#define MM (BB * SS)   // 8192

// Scratch (device globals: allocation-free per harness rules)
__device__ float g_q[(long long)BB * SS * DD];     // 32 MB
__device__ float g_k[(long long)BB * SS * DD];     // 32 MB
__device__ float g_v[(long long)BB * SS * DD];     // 32 MB
__device__ float g_att[(long long)BB * SS * DD];   // 32 MB
__device__ float g_s[(long long)BB * SS * SS];     // 64 MB

// ---------------------------------------------------------------------------
// Tiled SGEMM: C[M,N] = A[M,K] * op(B) (+ bias), batched via blockIdx.z.
//   TRANSB=false: B is [K,N] row-major
//   TRANSB=true : B is [N,K] row-major (C = A * B^T)
// Tile: BM=BN=128, BK=16, 256 threads, 8x8 per thread.
// All dims assumed multiples of the tile (true for this problem).
// ---------------------------------------------------------------------------
template <bool TRANSB, bool BIAS>
__global__ void __launch_bounds__(256, 2)
gemm_kernel(const float* __restrict__ A,
            const float* __restrict__ Bm,
            const float* __restrict__ bias,
            float* __restrict__ C,
            int M, int N, int K,
            long long sA, long long sB, long long sC)
{
    constexpr int BM = 128, BN = 128, BK = 16;

    A  += (long long)blockIdx.z * sA;
    Bm += (long long)blockIdx.z * sB;
    C  += (long long)blockIdx.z * sC;

    const int bm = blockIdx.y * BM;
    const int bn = blockIdx.x * BN;

    __shared__ float As[BK][BM + 4];
    __shared__ float Bs[BK][BN + 4];

    const int t  = threadIdx.x;
    const int tx = t & 15;        // 0..15 -> column group
    const int ty = t >> 4;        // 0..15 -> row group

    float acc[8][8];
#pragma unroll
    for (int i = 0; i < 8; i++)
#pragma unroll
        for (int j = 0; j < 8; j++)
            acc[i][j] = 0.0f;

    for (int k0 = 0; k0 < K; k0 += BK) {
        // ---- load A tile (BM x BK), store transposed As[k][m] ----
#pragma unroll
        for (int p = 0; p < 2; p++) {
            int aRow = (t >> 2) + p * 64;      // 0..127
            int aCol = (t & 3) * 4;            // 0,4,8,12
            float4 va = *(const float4*)&A[(long long)(bm + aRow) * K + k0 + aCol];
            As[aCol + 0][aRow] = va.x;
            As[aCol + 1][aRow] = va.y;
            As[aCol + 2][aRow] = va.z;
            As[aCol + 3][aRow] = va.w;
        }
        // ---- load B tile into Bs[k][n] ----
        if (TRANSB) {
            // B is [N,K]; element (k,n) = B[(bn+n)*K + k0+k]
#pragma unroll
            for (int p = 0; p < 2; p++) {
                int bRow = (t >> 2) + p * 64;  // n: 0..127
                int bCol = (t & 3) * 4;        // k: 0,4,8,12
                float4 vb = *(const float4*)&Bm[(long long)(bn + bRow) * K + k0 + bCol];
                Bs[bCol + 0][bRow] = vb.x;
                Bs[bCol + 1][bRow] = vb.y;
                Bs[bCol + 2][bRow] = vb.z;
                Bs[bCol + 3][bRow] = vb.w;
            }
        } else {
            // B is [K,N]; element (k,n) = B[(k0+k)*N + bn+n]
#pragma unroll
            for (int p = 0; p < 2; p++) {
                int bRow = (t >> 5) + p * 8;   // k: 0..15
                int bCol = (t & 31) * 4;       // n: 0..124
                float4 vb = *(const float4*)&Bm[(long long)(k0 + bRow) * N + bn + bCol];
                *(float4*)&Bs[bRow][bCol] = vb;
            }
        }
        __syncthreads();

        // ---- compute ----
#pragma unroll
        for (int kk = 0; kk < BK; kk++) {
            float ar[8], br[8];
            *(float4*)&ar[0] = *(const float4*)&As[kk][ty * 8];
            *(float4*)&ar[4] = *(const float4*)&As[kk][ty * 8 + 4];
            *(float4*)&br[0] = *(const float4*)&Bs[kk][tx * 8];
            *(float4*)&br[4] = *(const float4*)&Bs[kk][tx * 8 + 4];
#pragma unroll
            for (int i = 0; i < 8; i++)
#pragma unroll
                for (int j = 0; j < 8; j++)
                    acc[i][j] = fmaf(ar[i], br[j], acc[i][j]);
        }
        __syncthreads();
    }

    // ---- epilogue ----
#pragma unroll
    for (int i = 0; i < 8; i++) {
        long long crow = (long long)(bm + ty * 8 + i) * N + bn;
#pragma unroll
        for (int j = 0; j < 8; j += 4) {
            float4 v;
            v.x = acc[i][j + 0];
            v.y = acc[i][j + 1];
            v.z = acc[i][j + 2];
            v.w = acc[i][j + 3];
            if (BIAS) {
                int c = bn + tx * 8 + j;
                v.x += bias[c + 0];
                v.y += bias[c + 1];
                v.z += bias[c + 2];
                v.w += bias[c + 3];
            }
            *(float4*)&C[crow + tx * 8 + j] = v;
        }
    }
}

// ---------------------------------------------------------------------------
// Row softmax over `cols` (=2048) elements. One 256-thread block per row.
// ---------------------------------------------------------------------------
__global__ void __launch_bounds__(256)
softmax_kernel(float* __restrict__ data, int cols)
{
    const long long row = blockIdx.x;
    float* p = data + row * (long long)cols;
    const int t = threadIdx.x;       // 256 threads, 8 elems each

    float v[8];
    float vmax = -3.4e38f;
#pragma unroll
    for (int i = 0; i < 8; i++) {
        v[i] = p[t + i * 256];
        vmax = fmaxf(vmax, v[i]);
    }

    __shared__ float red[256];
    red[t] = vmax;
    __syncthreads();
#pragma unroll
    for (int s = 128; s > 0; s >>= 1) {
        if (t < s) red[t] = fmaxf(red[t], red[t + s]);
        __syncthreads();
    }
    vmax = red[0];
    __syncthreads();

    float sum = 0.0f;
#pragma unroll
    for (int i = 0; i < 8; i++) {
        v[i] = __expf(v[i] - vmax);
        sum += v[i];
    }
    red[t] = sum;
    __syncthreads();
#pragma unroll
    for (int s = 128; s > 0; s >>= 1) {
        if (t < s) red[t] += red[t + s];
        __syncthreads();
    }
    const float inv = 1.0f / red[0];

#pragma unroll
    for (int i = 0; i < 8; i++)
        p[t + i * 256] = v[i] * inv;
}

// ---------------------------------------------------------------------------
extern "C" void kernel_launch(void* const* d_in, const int* in_sizes, int n_in,
                              void* d_out, int out_size)
{
    const float* query = (const float*)d_in[0];
    const float* keys  = (const float*)d_in[1];
    const float* values= (const float*)d_in[2];
    const float* Wq    = (const float*)d_in[3];
    const float* bq    = (const float*)d_in[4];
    const float* Wk    = (const float*)d_in[5];
    const float* bk    = (const float*)d_in[6];
    const float* Wv    = (const float*)d_in[7];
    const float* bv    = (const float*)d_in[8];
    const float* Wd    = (const float*)d_in[9];
    const float* bd    = (const float*)d_in[10];
    float* out = (float*)d_out;

    float *q, *k, *v, *att, *s;
    cudaGetSymbolAddress((void**)&q,   g_q);
    cudaGetSymbolAddress((void**)&k,   g_k);
    cudaGetSymbolAddress((void**)&v,   g_v);
    cudaGetSymbolAddress((void**)&att, g_att);
    cudaGetSymbolAddress((void**)&s,   g_s);

    const long long strideQKV = (long long)SS * DD;  // per-batch q/k/v/att stride
    const long long strideS   = (long long)SS * SS;  // per-batch scores stride

    dim3 blk(256);

    // 1) Projections: [8192,1024] = [8192,1024] x [1024,1024] + bias
    {
        dim3 grid(DD / 128, MM / 128, 1);
        gemm_kernel<false, true><<<grid, blk>>>(query,  Wq, bq, q, MM, DD, DD, 0, 0, 0);
        gemm_kernel<false, true><<<grid, blk>>>(keys,   Wk, bk, k, MM, DD, DD, 0, 0, 0);
        gemm_kernel<false, true><<<grid, blk>>>(values, Wv, bv, v, MM, DD, DD, 0, 0, 0);
    }

    // 2) scores[b] = q[b] @ k[b]^T  : [2048,2048], K=1024
    {
        dim3 grid(SS / 128, SS / 128, BB);
        gemm_kernel<true, false><<<grid, blk>>>(q, k, nullptr, s,
                                                SS, SS, DD,
                                                strideQKV, strideQKV, strideS);
    }

    // 3) softmax rows (in place)
    softmax_kernel<<<BB * SS, blk>>>(s, SS);

    // 4) attended[b] = attn[b] @ v[b] : [2048,1024], K=2048
    {
        dim3 grid(DD / 128, SS / 128, BB);
        gemm_kernel<false, false><<<grid, blk>>>(s, v, nullptr, att,
                                                 SS, DD, SS,
                                                 strideS, strideQKV, strideQKV);
    }

    // 5) out = attended @ Wd + bd : [8192,1024], K=1024
    {
        dim3 grid(DD / 128, MM / 128, 1);
        gemm_kernel<false, true><<<grid, blk>>>(att, Wd, bd, out, MM, DD, DD, 0, 0, 0);
    }
}

// round 3
// speedup vs baseline: 1.7507x; 1.7507x over previous
#include <cuda_runtime.h>
#include <cuda_fp16.h>
#include <cstdint>

#define BB 4
#define SS 2048
#define DD 1024
#define MM (BB * SS)

// ---------------- scratch (device globals; allocation-free) ----------------
__device__ float g_q  [(size_t)MM * DD];
__device__ float g_k  [(size_t)MM * DD];
__device__ float g_v  [(size_t)MM * DD];
__device__ float g_att[(size_t)MM * DD];
__device__ float g_s  [(size_t)BB * SS * SS];
__device__ float g_wtq[(size_t)DD * DD];
__device__ float g_wtk[(size_t)DD * DD];
__device__ float g_wtv[(size_t)DD * DD];
__device__ float g_wtd[(size_t)DD * DD];
__device__ float g_vt [(size_t)MM * DD];

#define MMA16816(d, a, b) \
    asm volatile("mma.sync.aligned.m16n8k16.row.col.f32.f16.f16.f32 " \
                 "{%0,%1,%2,%3}, {%4,%5,%6,%7}, {%8,%9}, {%0,%1,%2,%3};" \
                 : "+f"((d)[0]), "+f"((d)[1]), "+f"((d)[2]), "+f"((d)[3]) \
                 : "r"((a)[0]), "r"((a)[1]), "r"((a)[2]), "r"((a)[3]), \
                   "r"((b)[0]), "r"((b)[1]))

// ---------------------------------------------------------------------------
// fp16x3-split tensor-core GEMM: C[m,n] = sum_k A[m,k]*B[n,k] (+bias)
// A: [M,K] row-major fp32.  B: [N,K] row-major fp32 (pre-transposed).
// Block tile 128x128x32, 256 threads (8 warps, 2x4), warp tile 64x32.
// Smem: per buffer, A and B tiles of 128 rows x 64 halfs (hi cols 0..31,
// lo cols 32..63), row stride 72 halfs; double buffered.
// ---------------------------------------------------------------------------
template <bool BIAS>
__global__ void __launch_bounds__(256)
hgemm_kernel(const float* __restrict__ A, const float* __restrict__ B,
             const float* __restrict__ bias, float* __restrict__ C,
             int M, int N, int K,
             long long sA, long long sB, long long sC)
{
    extern __shared__ __half sm[];
    constexpr int LDA  = 72;           // halfs per smem row
    constexpr int TILEH = 128 * LDA;   // halfs per A (or B) tile

    A += (long long)blockIdx.z * sA;
    B += (long long)blockIdx.z * sB;
    C += (long long)blockIdx.z * sC;

    const int bm = blockIdx.y * 128;
    const int bn = blockIdx.x * 128;
    const int t    = threadIdx.x;
    const int lane = t & 31;
    const int wid  = t >> 5;
    const int widM = wid & 1;          // 0..1 -> M offset *64
    const int widN = wid >> 1;         // 0..3 -> N offset *32
    const int g = lane >> 2;           // 0..7
    const int q = lane & 3;            // 0..3

    // global-load mapping: each thread handles one row-half (16 fp32)
    const int lrow  = t >> 1;          // 0..127
    const int lhalf = t & 1;           // cols [0..15] or [16..31]
    const float* Ag = A + (long long)(bm + lrow) * K + lhalf * 16;
    const float* Bg = B + (long long)(bn + lrow) * K + lhalf * 16;

    float acc[4][4][4];
#pragma unroll
    for (int i = 0; i < 4; i++)
#pragma unroll
        for (int j = 0; j < 4; j++)
#pragma unroll
            for (int r = 0; r < 4; r++)
                acc[i][j][r] = 0.0f;

    const int nIter = K >> 5;

    float4 ra[4], rb[4];

    auto load_regs = [&](int it) {
        const long long ko = (long long)it * 32;
#pragma unroll
        for (int i = 0; i < 4; i++) {
            ra[i] = *(const float4*)(Ag + ko + 4 * i);
            rb[i] = *(const float4*)(Bg + ko + 4 * i);
        }
    };
    auto store_tile = [&](int b) {
        __half* As = sm + (size_t)b * (2 * TILEH);
        __half* Bs = As + TILEH;
        __half* pa = As + lrow * LDA + lhalf * 16;
        __half* pb = Bs + lrow * LDA + lhalf * 16;
#pragma unroll
        for (int i = 0; i < 4; i++) {
            float4 v = ra[i];
            __half2 h0 = __floats2half2_rn(v.x, v.y);
            __half2 h1 = __floats2half2_rn(v.z, v.w);
            float2 f0 = __half22float2(h0);
            float2 f1 = __half22float2(h1);
            __half2 l0 = __floats2half2_rn(v.x - f0.x, v.y - f0.y);
            __half2 l1 = __floats2half2_rn(v.z - f1.x, v.w - f1.y);
            *(__half2*)(pa + 4 * i)          = h0;
            *(__half2*)(pa + 4 * i + 2)      = h1;
            *(__half2*)(pa + 32 + 4 * i)     = l0;
            *(__half2*)(pa + 32 + 4 * i + 2) = l1;

            v = rb[i];
            h0 = __floats2half2_rn(v.x, v.y);
            h1 = __floats2half2_rn(v.z, v.w);
            f0 = __half22float2(h0);
            f1 = __half22float2(h1);
            l0 = __floats2half2_rn(v.x - f0.x, v.y - f0.y);
            l1 = __floats2half2_rn(v.z - f1.x, v.w - f1.y);
            *(__half2*)(pb + 4 * i)          = h0;
            *(__half2*)(pb + 4 * i + 2)      = h1;
            *(__half2*)(pb + 32 + 4 * i)     = l0;
            *(__half2*)(pb + 32 + 4 * i + 2) = l1;
        }
    };

    // prologue
    load_regs(0);
    store_tile(0);
    __syncthreads();

    for (int it = 0; it < nIter; ++it) {
        if (it + 1 < nIter) load_regs(it + 1);

        // ---- compute on buffer it&1 ----
        {
            const __half* As = sm + (size_t)(it & 1) * (2 * TILEH);
            const __half* Bs = As + TILEH;
            const __half* aw = As + (widM * 64) * LDA;
            const __half* bw = Bs + (widN * 32) * LDA;
#pragma unroll
            for (int kk = 0; kk < 2; ++kk) {
                const int kc = kk * 16 + 2 * q;
                uint32_t bh[4][2], bl[4][2];
#pragma unroll
                for (int nt = 0; nt < 4; ++nt) {
                    const __half* pb0 = bw + (nt * 8 + g) * LDA;
                    bh[nt][0] = *(const uint32_t*)(pb0 + kc);
                    bh[nt][1] = *(const uint32_t*)(pb0 + kc + 8);
                    bl[nt][0] = *(const uint32_t*)(pb0 + 32 + kc);
                    bl[nt][1] = *(const uint32_t*)(pb0 + 32 + kc + 8);
                }
#pragma unroll
                for (int mt = 0; mt < 4; ++mt) {
                    const __half* pa0 = aw + (mt * 16 + g) * LDA;
                    const __half* pa1 = pa0 + 8 * LDA;
                    uint32_t ah[4], al[4];
                    ah[0] = *(const uint32_t*)(pa0 + kc);
                    ah[1] = *(const uint32_t*)(pa1 + kc);
                    ah[2] = *(const uint32_t*)(pa0 + kc + 8);
                    ah[3] = *(const uint32_t*)(pa1 + kc + 8);
                    al[0] = *(const uint32_t*)(pa0 + 32 + kc);
                    al[1] = *(const uint32_t*)(pa1 + 32 + kc);
                    al[2] = *(const uint32_t*)(pa0 + 32 + kc + 8);
                    al[3] = *(const uint32_t*)(pa1 + 32 + kc + 8);
#pragma unroll
                    for (int nt = 0; nt < 4; ++nt) {
                        MMA16816(acc[mt][nt], ah, bh[nt]);
                        MMA16816(acc[mt][nt], ah, bl[nt]);
                        MMA16816(acc[mt][nt], al, bh[nt]);
                    }
                }
            }
        }

        if (it + 1 < nIter) store_tile((it + 1) & 1);
        __syncthreads();
    }

    // ---- epilogue: direct float2 stores (+bias) ----
#pragma unroll
    for (int nt = 0; nt < 4; ++nt) {
        const int col = bn + widN * 32 + nt * 8 + 2 * q;
        float b0 = 0.f, b1 = 0.f;
        if (BIAS) { b0 = bias[col]; b1 = bias[col + 1]; }
#pragma unroll
        for (int mt = 0; mt < 4; ++mt) {
            const int row0 = bm + widM * 64 + mt * 16 + g;
            float* p0 = C + (long long)row0 * N + col;
            float* p1 = p0 + (long long)8 * N;
            float2 v0 = make_float2(acc[mt][nt][0] + b0, acc[mt][nt][1] + b1);
            float2 v1 = make_float2(acc[mt][nt][2] + b0, acc[mt][nt][3] + b1);
            *(float2*)p0 = v0;
            *(float2*)p1 = v1;
        }
    }
}

// ---------------------------------------------------------------------------
// 32x32 tiled transpose: out[c][r] = in[r][c], batched via blockIdx.z
// ---------------------------------------------------------------------------
__global__ void __launch_bounds__(256)
transpose_kernel(const float* __restrict__ in, float* __restrict__ out,
                 int R, int Cc, long long sIn, long long sOut)
{
    __shared__ float tbuf[32][33];
    in  += (long long)blockIdx.z * sIn;
    out += (long long)blockIdx.z * sOut;
    const int c0 = blockIdx.x * 32;
    const int r0 = blockIdx.y * 32;
    const int x = threadIdx.x & 31;
    const int y = threadIdx.x >> 5;
#pragma unroll
    for (int j = 0; j < 32; j += 8)
        tbuf[y + j][x] = in[(long long)(r0 + y + j) * Cc + c0 + x];
    __syncthreads();
#pragma unroll
    for (int j = 0; j < 32; j += 8)
        out[(long long)(c0 + y + j) * R + r0 + x] = tbuf[x][y + j];
}

// ---------------------------------------------------------------------------
// Row softmax over 2048 cols. One 256-thread block per row.
// ---------------------------------------------------------------------------
__global__ void __launch_bounds__(256)
softmax_kernel(float* __restrict__ data, int cols)
{
    const long long row = blockIdx.x;
    float* p = data + row * (long long)cols;
    const int t = threadIdx.x;

    float v[8];
    float vmax = -3.4e38f;
#pragma unroll
    for (int i = 0; i < 8; i++) {
        v[i] = p[t + i * 256];
        vmax = fmaxf(vmax, v[i]);
    }
    __shared__ float red[256];
    red[t] = vmax;
    __syncthreads();
#pragma unroll
    for (int s = 128; s > 0; s >>= 1) {
        if (t < s) red[t] = fmaxf(red[t], red[t + s]);
        __syncthreads();
    }
    vmax = red[0];
    __syncthreads();

    float sum = 0.0f;
#pragma unroll
    for (int i = 0; i < 8; i++) {
        v[i] = __expf(v[i] - vmax);
        sum += v[i];
    }
    red[t] = sum;
    __syncthreads();
#pragma unroll
    for (int s = 128; s > 0; s >>= 1) {
        if (t < s) red[t] += red[t + s];
        __syncthreads();
    }
    const float inv = 1.0f / red[0];
#pragma unroll
    for (int i = 0; i < 8; i++)
        p[t + i * 256] = v[i] * inv;
}

// ---------------------------------------------------------------------------
extern "C" void kernel_launch(void* const* d_in, const int* in_sizes, int n_in,
                              void* d_out, int out_size)
{
    const float* query  = (const float*)d_in[0];
    const float* keys   = (const float*)d_in[1];
    const float* values = (const float*)d_in[2];
    const float* Wq = (const float*)d_in[3];
    const float* bq = (const float*)d_in[4];
    const float* Wk = (const float*)d_in[5];
    const float* bk = (const float*)d_in[6];
    const float* Wv = (const float*)d_in[7];
    const float* bv = (const float*)d_in[8];
    const float* Wd = (const float*)d_in[9];
    const float* bd = (const float*)d_in[10];
    float* out = (float*)d_out;

    float *q, *k, *v, *att, *s, *wtq, *wtk, *wtv, *wtd, *vt;
    cudaGetSymbolAddress((void**)&q,   g_q);
    cudaGetSymbolAddress((void**)&k,   g_k);
    cudaGetSymbolAddress((void**)&v,   g_v);
    cudaGetSymbolAddress((void**)&att, g_att);
    cudaGetSymbolAddress((void**)&s,   g_s);
    cudaGetSymbolAddress((void**)&wtq, g_wtq);
    cudaGetSymbolAddress((void**)&wtk, g_wtk);
    cudaGetSymbolAddress((void**)&wtv, g_wtv);
    cudaGetSymbolAddress((void**)&wtd, g_wtd);
    cudaGetSymbolAddress((void**)&vt,  g_vt);

    const int smemBytes = 2 * 2 * 128 * 72 * (int)sizeof(__half);  // 73728
    cudaFuncSetAttribute(hgemm_kernel<true>,
                         cudaFuncAttributeMaxDynamicSharedMemorySize, smemBytes);
    cudaFuncSetAttribute(hgemm_kernel<false>,
                         cudaFuncAttributeMaxDynamicSharedMemorySize, smemBytes);

    const long long strideQKV = (long long)SS * DD;
    const long long strideS   = (long long)SS * SS;

    dim3 tb(256);
    // 0) transpose weights -> [N,K]
    {
        dim3 gt(DD / 32, DD / 32, 1);
        transpose_kernel<<<gt, tb>>>(Wq, wtq, DD, DD, 0, 0);
        transpose_kernel<<<gt, tb>>>(Wk, wtk, DD, DD, 0, 0);
        transpose_kernel<<<gt, tb>>>(Wv, wtv, DD, DD, 0, 0);
        transpose_kernel<<<gt, tb>>>(Wd, wtd, DD, DD, 0, 0);
    }

    // 1) projections: [8192,1024] x [1024,1024]^T(+b)
    {
        dim3 gg(DD / 128, MM / 128, 1);
        hgemm_kernel<true><<<gg, tb, smemBytes>>>(query,  wtq, bq, q, MM, DD, DD, 0, 0, 0);
        hgemm_kernel<true><<<gg, tb, smemBytes>>>(keys,   wtk, bk, k, MM, DD, DD, 0, 0, 0);
        hgemm_kernel<true><<<gg, tb, smemBytes>>>(values, wtv, bv, v, MM, DD, DD, 0, 0, 0);
    }

    // 2) scores = q @ k^T per batch (k already [N,K])
    {
        dim3 gg(SS / 128, SS / 128, BB);
        hgemm_kernel<false><<<gg, tb, smemBytes>>>(q, k, nullptr, s,
                                                   SS, SS, DD,
                                                   strideQKV, strideQKV, strideS);
    }

    // 3) softmax rows (in place)
    softmax_kernel<<<BB * SS, tb>>>(s, SS);

    // 4) v^T per batch: [S,D] -> [D,S]
    {
        dim3 gt(DD / 32, SS / 32, BB);
        transpose_kernel<<<gt, tb>>>(v, vt, SS, DD, strideQKV, strideQKV);
    }

    // 5) attended = attn @ v  (B = v^T : [N=D, K=S])
    {
        dim3 gg(DD / 128, SS / 128, BB);
        hgemm_kernel<false><<<gg, tb, smemBytes>>>(s, vt, nullptr, att,
                                                   SS, DD, SS,
                                                   strideS, strideQKV, strideQKV);
    }

    // 6) out = attended @ Wd + bd
    {
        dim3 gg(DD / 128, MM / 128, 1);
        hgemm_kernel<true><<<gg, tb, smemBytes>>>(att, wtd, bd, out, MM, DD, DD, 0, 0, 0);
    }
}

// round 5
// speedup vs baseline: 2.4253x; 1.3854x over previous
#include <cuda_runtime.h>
#include <cuda_fp16.h>
#include <cstdint>

#define BB 4
#define SS 2048
#define DD 1024
#define MM (BB * SS)

// ---------------- scratch (device globals; allocation-free) ----------------
// hi/lo fp16 planes
__device__ __half g_inq_h[(size_t)MM * DD], g_inq_l[(size_t)MM * DD];
__device__ __half g_ink_h[(size_t)MM * DD], g_ink_l[(size_t)MM * DD];
__device__ __half g_inv_h[(size_t)MM * DD], g_inv_l[(size_t)MM * DD];
__device__ __half g_wq_h[(size_t)DD * DD],  g_wq_l[(size_t)DD * DD];
__device__ __half g_wk_h[(size_t)DD * DD],  g_wk_l[(size_t)DD * DD];
__device__ __half g_wv_h[(size_t)DD * DD],  g_wv_l[(size_t)DD * DD];
__device__ __half g_wd_h[(size_t)DD * DD],  g_wd_l[(size_t)DD * DD];
__device__ __half g_q_h[(size_t)MM * DD],   g_q_l[(size_t)MM * DD];
__device__ __half g_k_h[(size_t)MM * DD],   g_k_l[(size_t)MM * DD];
__device__ __half g_vt_h[(size_t)MM * DD],  g_vt_l[(size_t)MM * DD];
__device__ __half g_s_h[(size_t)BB * SS * SS], g_s_l[(size_t)BB * SS * SS];
__device__ __half g_att_h[(size_t)MM * DD], g_att_l[(size_t)MM * DD];
// fp32 intermediates
__device__ float g_v[(size_t)MM * DD];
__device__ float g_s[(size_t)BB * SS * SS];

// ---------------- asm helpers ----------------
#define MMA16816(d, a, b) \
    asm volatile("mma.sync.aligned.m16n8k16.row.col.f32.f16.f16.f32 " \
                 "{%0,%1,%2,%3}, {%4,%5,%6,%7}, {%8,%9}, {%0,%1,%2,%3};" \
                 : "+f"((d)[0]), "+f"((d)[1]), "+f"((d)[2]), "+f"((d)[3]) \
                 : "r"((a)[0]), "r"((a)[1]), "r"((a)[2]), "r"((a)[3]), \
                   "r"((b)[0]), "r"((b)[1]))

#define LDSM4(r0, r1, r2, r3, addr) \
    asm volatile("ldmatrix.sync.aligned.m8n8.x4.shared.b16 {%0,%1,%2,%3}, [%4];" \
                 : "=r"(r0), "=r"(r1), "=r"(r2), "=r"(r3) : "r"(addr))

#define CPA16(dst, src) \
    asm volatile("cp.async.cg.shared.global [%0], [%1], 16;" \
                 :: "r"(dst), "l"(src) : "memory")
#define CPA_COMMIT() asm volatile("cp.async.commit_group;" ::: "memory")
#define CPA_WAIT1()  asm volatile("cp.async.wait_group 1;" ::: "memory")

__device__ __forceinline__ uint32_t smem_u32(const void* p) {
    uint32_t a;
    asm("{ .reg .u64 t; cvta.to.shared.u64 t, %1; cvt.u32.u64 %0, t; }"
        : "=r"(a) : "l"(p));
    return a;
}
// swizzled chunk address: plane rows of 32 halfs (64B) = 4 chunks of 16B
__device__ __forceinline__ uint32_t sw_addr(uint32_t plane, int row, int c) {
    return plane + (uint32_t)((row * 4 + (c ^ ((row >> 1) & 3))) * 16);
}

// ---------------------------------------------------------------------------
// fp16x3-split tensor GEMM on pre-split hi/lo planes.
// C[m,n] = sum_k A[m,k]*B[n,k] (+bias); A,B given as hi/lo fp16 [.,K] row-major.
// OMODE 0: fp32 out.  OMODE 1: hi/lo fp16 plane out.
// 128x128x32 tile, 256 thr (8 warps 2x4), cp.async 3-stage, ldmatrix.
// ---------------------------------------------------------------------------
template <int OMODE, bool BIAS>
__global__ void __launch_bounds__(256, 2)
hgemm_kernel(const __half* __restrict__ Ahi, const __half* __restrict__ Alo,
             const __half* __restrict__ Bhi, const __half* __restrict__ Blo,
             const float* __restrict__ bias,
             float* __restrict__ Cf, __half* __restrict__ Chi, __half* __restrict__ Clo,
             int M, int N, int K,
             long long sA, long long sB, long long sC)
{
    constexpr int PLANE = 8192;            // 128 rows * 64B
    constexpr int STAGE = 4 * PLANE;       // Ahi|Alo|Bhi|Blo
    extern __shared__ char smem[];
    const uint32_t sbase = smem_u32(smem);

    Ahi += (long long)blockIdx.z * sA;  Alo += (long long)blockIdx.z * sA;
    Bhi += (long long)blockIdx.z * sB;  Blo += (long long)blockIdx.z * sB;
    if (OMODE == 0) Cf += (long long)blockIdx.z * sC;
    else { Chi += (long long)blockIdx.z * sC; Clo += (long long)blockIdx.z * sC; }

    const int bm = blockIdx.y * 128;
    const int bn = blockIdx.x * 128;
    const int t    = threadIdx.x;
    const int lane = t & 31;
    const int wid  = t >> 5;
    const int widM = wid & 1;
    const int widN = wid >> 1;
    const int g  = lane >> 2;
    const int qq = lane & 3;
    const int l7   = lane & 7;
    const int lsel = (lane >> 3) & 1;
    const int lch  = lane >> 4;

    // cp.async mapping: thread covers (row = t>>2, chunk = t&3) for 8 (plane,rowhalf) pairs
    const int cr = t >> 2;    // 0..63
    const int cc = t & 3;     // chunk in row

    const __half* srcb[4] = { Ahi + (long long)bm * K, Alo + (long long)bm * K,
                              Bhi + (long long)bn * K, Blo + (long long)bn * K };

    auto issue = [&](int kt, int slot) {
        const uint32_t dstb = sbase + (uint32_t)slot * STAGE;
        const long long koff = (long long)kt * 32 + cc * 8;
#pragma unroll
        for (int i = 0; i < 8; ++i) {
            const int p = i >> 1;
            const int r = (i & 1) * 64 + cr;
            const __half* src = srcb[p] + (long long)r * K + koff;
            CPA16(sw_addr(dstb + p * PLANE, r, cc), src);
        }
    };

    float acc[4][4][4];
#pragma unroll
    for (int i = 0; i < 4; i++)
#pragma unroll
        for (int j = 0; j < 4; j++)
#pragma unroll
            for (int r = 0; r < 4; r++) acc[i][j][r] = 0.0f;

    const int nIter = K >> 5;
    const int m0 = widM * 64;
    const int n0 = widN * 32;

    issue(0, 0); CPA_COMMIT();
    issue(1, 1); CPA_COMMIT();

    for (int it = 0; it < nIter; ++it) {
        CPA_WAIT1();
        __syncthreads();
        if (it + 2 < nIter) issue(it + 2, (it + 2) % 3);
        CPA_COMMIT();

        const uint32_t stb = sbase + (uint32_t)(it % 3) * STAGE;
        const uint32_t pAhi = stb, pAlo = stb + PLANE;
        const uint32_t pBhi = stb + 2 * PLANE, pBlo = stb + 3 * PLANE;

#pragma unroll
        for (int kk = 0; kk < 2; ++kk) {
            const int c = 2 * kk + lch;
            uint32_t bh[4][2], bl[4][2];
#pragma unroll
            for (int np = 0; np < 2; ++np) {
                const int row = n0 + np * 16 + l7 + lsel * 8;
                uint32_t r0, r1, r2, r3;
                LDSM4(r0, r1, r2, r3, sw_addr(pBhi, row, c));
                bh[np * 2][0] = r0; bh[np * 2][1] = r2;
                bh[np * 2 + 1][0] = r1; bh[np * 2 + 1][1] = r3;
                LDSM4(r0, r1, r2, r3, sw_addr(pBlo, row, c));
                bl[np * 2][0] = r0; bl[np * 2][1] = r2;
                bl[np * 2 + 1][0] = r1; bl[np * 2 + 1][1] = r3;
            }
#pragma unroll
            for (int mt = 0; mt < 4; ++mt) {
                const int row = m0 + mt * 16 + l7 + lsel * 8;
                uint32_t ah[4], al[4];
                LDSM4(ah[0], ah[1], ah[2], ah[3], sw_addr(pAhi, row, c));
                LDSM4(al[0], al[1], al[2], al[3], sw_addr(pAlo, row, c));
#pragma unroll
                for (int nt = 0; nt < 4; ++nt) {
                    MMA16816(acc[mt][nt], ah, bh[nt]);
                    MMA16816(acc[mt][nt], ah, bl[nt]);
                    MMA16816(acc[mt][nt], al, bh[nt]);
                }
            }
        }
    }

    // ---- epilogue ----
#pragma unroll
    for (int nt = 0; nt < 4; ++nt) {
        const int col = bn + n0 + nt * 8 + 2 * qq;
        float b0 = 0.f, b1 = 0.f;
        if (BIAS) { b0 = bias[col]; b1 = bias[col + 1]; }
#pragma unroll
        for (int mt = 0; mt < 4; ++mt) {
            const int row0 = bm + m0 + mt * 16 + g;
            const float v0 = acc[mt][nt][0] + b0, v1 = acc[mt][nt][1] + b1;
            const float v2 = acc[mt][nt][2] + b0, v3 = acc[mt][nt][3] + b1;
            if (OMODE == 0) {
                *(float2*)(Cf + (long long)row0 * N + col)       = make_float2(v0, v1);
                *(float2*)(Cf + (long long)(row0 + 8) * N + col) = make_float2(v2, v3);
            } else {
                __half2 h0 = __floats2half2_rn(v0, v1);
                float2 f0 = __half22float2(h0);
                __half2 l0 = __floats2half2_rn(v0 - f0.x, v1 - f0.y);
                __half2 h1 = __floats2half2_rn(v2, v3);
                float2 f1 = __half22float2(h1);
                __half2 l1 = __floats2half2_rn(v2 - f1.x, v3 - f1.y);
                *(__half2*)(Chi + (long long)row0 * N + col)       = h0;
                *(__half2*)(Clo + (long long)row0 * N + col)       = l0;
                *(__half2*)(Chi + (long long)(row0 + 8) * N + col) = h1;
                *(__half2*)(Clo + (long long)(row0 + 8) * N + col) = l1;
            }
        }
    }
}

// ---------------------------------------------------------------------------
// fp32 -> hi/lo fp16 planes (elementwise, float4 granularity)
// ---------------------------------------------------------------------------
__global__ void __launch_bounds__(256)
convert_kernel(const float* __restrict__ in, __half* __restrict__ hi,
               __half* __restrict__ lo, size_t n4)
{
    size_t i = (size_t)blockIdx.x * blockDim.x + threadIdx.x;
    if (i >= n4) return;
    float4 v = ((const float4*)in)[i];
    __half2 h0 = __floats2half2_rn(v.x, v.y), h1 = __floats2half2_rn(v.z, v.w);
    float2 f0 = __half22float2(h0), f1 = __half22float2(h1);
    __half2 l0 = __floats2half2_rn(v.x - f0.x, v.y - f0.y);
    __half2 l1 = __floats2half2_rn(v.z - f1.x, v.w - f1.y);
    ((__half2*)hi)[2 * i] = h0; ((__half2*)hi)[2 * i + 1] = h1;
    ((__half2*)lo)[2 * i] = l0; ((__half2*)lo)[2 * i + 1] = l1;
}

// ---------------------------------------------------------------------------
// fp32 [R,C] -> transposed hi/lo fp16 [C,R]; batched via blockIdx.z
// ---------------------------------------------------------------------------
__global__ void __launch_bounds__(256)
transpose_convert_kernel(const float* __restrict__ in, __half* __restrict__ hi,
                         __half* __restrict__ lo, int R, int Cc,
                         long long sIn, long long sOut)
{
    __shared__ float tb[32][33];
    in += (long long)blockIdx.z * sIn;
    hi += (long long)blockIdx.z * sOut;
    lo += (long long)blockIdx.z * sOut;
    const int c0 = blockIdx.x * 32;
    const int r0 = blockIdx.y * 32;
    const int x = threadIdx.x & 31;
    const int y = threadIdx.x >> 5;
#pragma unroll
    for (int j = 0; j < 32; j += 8)
        tb[y + j][x] = in[(long long)(r0 + y + j) * Cc + c0 + x];
    __syncthreads();
#pragma unroll
    for (int j = 0; j < 32; j += 8) {
        const float v = tb[x][y + j];
        const __half h = __float2half_rn(v);
        const __half l = __float2half_rn(v - __half2float(h));
        const long long o = (long long)(c0 + y + j) * R + r0 + x;
        hi[o] = h; lo[o] = l;
    }
}

// ---------------------------------------------------------------------------
// Row softmax over 2048 cols, fp32 in -> hi/lo fp16 out.
// ---------------------------------------------------------------------------
__global__ void __launch_bounds__(256)
softmax_hilo_kernel(const float* __restrict__ in, __half* __restrict__ hi,
                    __half* __restrict__ lo, int cols)
{
    const long long row = blockIdx.x;
    const float* p = in + row * (long long)cols;
    const int t = threadIdx.x;

    float v[8];
    float vmax = -3.4e38f;
#pragma unroll
    for (int i = 0; i < 8; i++) {
        v[i] = p[t + i * 256];
        vmax = fmaxf(vmax, v[i]);
    }
    __shared__ float red[256];
    red[t] = vmax;
    __syncthreads();
#pragma unroll
    for (int s = 128; s > 0; s >>= 1) {
        if (t < s) red[t] = fmaxf(red[t], red[t + s]);
        __syncthreads();
    }
    vmax = red[0];
    __syncthreads();

    float sum = 0.0f;
#pragma unroll
    for (int i = 0; i < 8; i++) {
        v[i] = __expf(v[i] - vmax);
        sum += v[i];
    }
    red[t] = sum;
    __syncthreads();
#pragma unroll
    for (int s = 128; s > 0; s >>= 1) {
        if (t < s) red[t] += red[t + s];
        __syncthreads();
    }
    const float inv = 1.0f / red[0];
#pragma unroll
    for (int i = 0; i < 8; i++) {
        const float val = v[i] * inv;
        const __half h = __float2half_rn(val);
        const __half l = __float2half_rn(val - __half2float(h));
        hi[row * (long long)cols + t + i * 256] = h;
        lo[row * (long long)cols + t + i * 256] = l;
    }
}

// ---------------------------------------------------------------------------
extern "C" void kernel_launch(void* const* d_in, const int* in_sizes, int n_in,
                              void* d_out, int out_size)
{
    const float* query  = (const float*)d_in[0];
    const float* keys   = (const float*)d_in[1];
    const float* values = (const float*)d_in[2];
    const float* Wq = (const float*)d_in[3];
    const float* bq = (const float*)d_in[4];
    const float* Wk = (const float*)d_in[5];
    const float* bk = (const float*)d_in[6];
    const float* Wv = (const float*)d_in[7];
    const float* bv = (const float*)d_in[8];
    const float* Wd = (const float*)d_in[9];
    const float* bd = (const float*)d_in[10];
    float* out = (float*)d_out;

    __half *inq_h, *inq_l, *ink_h, *ink_l, *inv_h, *inv_l;
    __half *wq_h, *wq_l, *wk_h, *wk_l, *wv_h, *wv_l, *wd_h, *wd_l;
    __half *q_h, *q_l, *k_h, *k_l, *vt_h, *vt_l, *s_h, *s_l, *att_h, *att_l;
    float *v, *s;
    cudaGetSymbolAddress((void**)&inq_h, g_inq_h); cudaGetSymbolAddress((void**)&inq_l, g_inq_l);
    cudaGetSymbolAddress((void**)&ink_h, g_ink_h); cudaGetSymbolAddress((void**)&ink_l, g_ink_l);
    cudaGetSymbolAddress((void**)&inv_h, g_inv_h); cudaGetSymbolAddress((void**)&inv_l, g_inv_l);
    cudaGetSymbolAddress((void**)&wq_h, g_wq_h); cudaGetSymbolAddress((void**)&wq_l, g_wq_l);
    cudaGetSymbolAddress((void**)&wk_h, g_wk_h); cudaGetSymbolAddress((void**)&wk_l, g_wk_l);
    cudaGetSymbolAddress((void**)&wv_h, g_wv_h); cudaGetSymbolAddress((void**)&wv_l, g_wv_l);
    cudaGetSymbolAddress((void**)&wd_h, g_wd_h); cudaGetSymbolAddress((void**)&wd_l, g_wd_l);
    cudaGetSymbolAddress((void**)&q_h, g_q_h);   cudaGetSymbolAddress((void**)&q_l, g_q_l);
    cudaGetSymbolAddress((void**)&k_h, g_k_h);   cudaGetSymbolAddress((void**)&k_l, g_k_l);
    cudaGetSymbolAddress((void**)&vt_h, g_vt_h); cudaGetSymbolAddress((void**)&vt_l, g_vt_l);
    cudaGetSymbolAddress((void**)&s_h, g_s_h);   cudaGetSymbolAddress((void**)&s_l, g_s_l);
    cudaGetSymbolAddress((void**)&att_h, g_att_h); cudaGetSymbolAddress((void**)&att_l, g_att_l);
    cudaGetSymbolAddress((void**)&v, g_v);
    cudaGetSymbolAddress((void**)&s, g_s);

    const int smemBytes = 3 * 4 * 8192;   // 98304
    cudaFuncSetAttribute(hgemm_kernel<0, true>,  cudaFuncAttributeMaxDynamicSharedMemorySize, smemBytes);
    cudaFuncSetAttribute(hgemm_kernel<0, false>, cudaFuncAttributeMaxDynamicSharedMemorySize, smemBytes);
    cudaFuncSetAttribute(hgemm_kernel<1, true>,  cudaFuncAttributeMaxDynamicSharedMemorySize, smemBytes);
    cudaFuncSetAttribute(hgemm_kernel<1, false>, cudaFuncAttributeMaxDynamicSharedMemorySize, smemBytes);

    const long long strideQKV = (long long)SS * DD;
    const long long strideS   = (long long)SS * SS;

    dim3 tb(256);

    // 0a) convert raw inputs -> hi/lo planes
    {
        const size_t n4 = (size_t)MM * DD / 4;
        const int gr = (int)((n4 + 255) / 256);
        convert_kernel<<<gr, tb>>>(query,  inq_h, inq_l, n4);
        convert_kernel<<<gr, tb>>>(keys,   ink_h, ink_l, n4);
        convert_kernel<<<gr, tb>>>(values, inv_h, inv_l, n4);
    }
    // 0b) transpose+convert weights -> [N,K] hi/lo
    {
        dim3 gt(DD / 32, DD / 32, 1);
        transpose_convert_kernel<<<gt, tb>>>(Wq, wq_h, wq_l, DD, DD, 0, 0);
        transpose_convert_kernel<<<gt, tb>>>(Wk, wk_h, wk_l, DD, DD, 0, 0);
        transpose_convert_kernel<<<gt, tb>>>(Wv, wv_h, wv_l, DD, DD, 0, 0);
        transpose_convert_kernel<<<gt, tb>>>(Wd, wd_h, wd_l, DD, DD, 0, 0);
    }

    // 1) projections: q,k -> hi/lo planes (+bias); v -> fp32 (+bias)
    {
        dim3 gg(DD / 128, MM / 128, 1);
        hgemm_kernel<1, true><<<gg, tb, smemBytes>>>(inq_h, inq_l, wq_h, wq_l, bq,
                                                     nullptr, q_h, q_l, MM, DD, DD, 0, 0, 0);
        hgemm_kernel<1, true><<<gg, tb, smemBytes>>>(ink_h, ink_l, wk_h, wk_l, bk,
                                                     nullptr, k_h, k_l, MM, DD, DD, 0, 0, 0);
        hgemm_kernel<0, true><<<gg, tb, smemBytes>>>(inv_h, inv_l, wv_h, wv_l, bv,
                                                     v, nullptr, nullptr, MM, DD, DD, 0, 0, 0);
    }

    // 2) scores = q @ k^T per batch -> fp32
    {
        dim3 gg(SS / 128, SS / 128, BB);
        hgemm_kernel<0, false><<<gg, tb, smemBytes>>>(q_h, q_l, k_h, k_l, nullptr,
                                                      s, nullptr, nullptr,
                                                      SS, SS, DD,
                                                      strideQKV, strideQKV, strideS);
    }

    // 3) softmax -> hi/lo planes
    softmax_hilo_kernel<<<BB * SS, tb>>>(s, s_h, s_l, SS);

    // 4) v^T per batch -> hi/lo [D,S]
    {
        dim3 gt(DD / 32, SS / 32, BB);
        transpose_convert_kernel<<<gt, tb>>>(v, vt_h, vt_l, SS, DD, strideQKV, strideQKV);
    }

    // 5) attended = attn @ v -> hi/lo planes
    {
        dim3 gg(DD / 128, SS / 128, BB);
        hgemm_kernel<1, false><<<gg, tb, smemBytes>>>(s_h, s_l, vt_h, vt_l, nullptr,
                                                      nullptr, att_h, att_l,
                                                      SS, DD, SS,
                                                      strideS, strideQKV, strideQKV);
    }

    // 6) out = attended @ Wd + bd -> fp32
    {
        dim3 gg(DD / 128, MM / 128, 1);
        hgemm_kernel<0, true><<<gg, tb, smemBytes>>>(att_h, att_l, wd_h, wd_l, bd,
                                                     out, nullptr, nullptr, MM, DD, DD, 0, 0, 0);
    }
}

// round 7
// speedup vs baseline: 2.7977x; 1.1535x over previous
#include <cuda_runtime.h>
#include <cuda_fp16.h>
#include <cstdint>

#define BB 4
#define SS 2048
#define DD 1024
#define MM (BB * SS)

// ---------------- scratch (device globals; allocation-free) ----------------
__device__ __half g_inq_h[(size_t)MM * DD], g_inq_l[(size_t)MM * DD];
__device__ __half g_ink_h[(size_t)MM * DD], g_ink_l[(size_t)MM * DD];
__device__ __half g_inv_h[(size_t)MM * DD], g_inv_l[(size_t)MM * DD];
__device__ __half g_wq_h[(size_t)DD * DD],  g_wq_l[(size_t)DD * DD];
__device__ __half g_wk_h[(size_t)DD * DD],  g_wk_l[(size_t)DD * DD];
__device__ __half g_wv_h[(size_t)DD * DD],  g_wv_l[(size_t)DD * DD];
__device__ __half g_wd_h[(size_t)DD * DD],  g_wd_l[(size_t)DD * DD];
__device__ __half g_q_h[(size_t)MM * DD],   g_q_l[(size_t)MM * DD];
__device__ __half g_k_h[(size_t)MM * DD],   g_k_l[(size_t)MM * DD];
__device__ __half g_vt_h[(size_t)MM * DD],  g_vt_l[(size_t)MM * DD];
__device__ __half g_s_h[(size_t)BB * SS * SS], g_s_l[(size_t)BB * SS * SS];
__device__ __half g_att_h[(size_t)MM * DD], g_att_l[(size_t)MM * DD];
__device__ float g_v[(size_t)MM * DD];
__device__ float g_s[(size_t)BB * SS * SS];

// ---------------- asm helpers ----------------
#define MMA16816(d, a, b) \
    asm volatile("mma.sync.aligned.m16n8k16.row.col.f32.f16.f16.f32 " \
                 "{%0,%1,%2,%3}, {%4,%5,%6,%7}, {%8,%9}, {%0,%1,%2,%3};" \
                 : "+f"((d)[0]), "+f"((d)[1]), "+f"((d)[2]), "+f"((d)[3]) \
                 : "r"((a)[0]), "r"((a)[1]), "r"((a)[2]), "r"((a)[3]), \
                   "r"((b)[0]), "r"((b)[1]))

#define LDSM4(r0, r1, r2, r3, addr) \
    asm volatile("ldmatrix.sync.aligned.m8n8.x4.shared.b16 {%0,%1,%2,%3}, [%4];" \
                 : "=r"(r0), "=r"(r1), "=r"(r2), "=r"(r3) : "r"(addr))

#define CPA16(dst, src) \
    asm volatile("cp.async.cg.shared.global [%0], [%1], 16;" \
                 :: "r"(dst), "l"(src) : "memory")
#define CPA_COMMIT() asm volatile("cp.async.commit_group;" ::: "memory")
#define CPA_WAIT1()  asm volatile("cp.async.wait_group 1;" ::: "memory")

__device__ __forceinline__ uint32_t smem_u32(const void* p) {
    uint32_t a;
    asm("{ .reg .u64 t; cvta.to.shared.u64 t, %1; cvt.u32.u64 %0, t; }"
        : "=r"(a) : "l"(p));
    return a;
}
__device__ __forceinline__ uint32_t sw_addr(uint32_t plane, int row, int c) {
    return plane + (uint32_t)((row * 4 + (c ^ ((row >> 1) & 3))) * 16);
}

// ---------------------------------------------------------------------------
// fp16-split tensor GEMM body (pre-split hi/lo operand planes).
// NPROD==3: C += Ah*Bh + Ah*Bl + Al*Bh   (full 3x split)
// NPROD==2: C += Ah*Bh + Ah*Bl           (A_lo dropped; plane not loaded)
// OMODE 0: fp32 out.  OMODE 1: hi/lo fp16 plane out.
// Tile 128x128x32, 256 thr (8 warps 2x4), cp.async 3-stage, ldmatrix.
// ---------------------------------------------------------------------------
template <int OMODE, bool BIAS, int NPROD>
__device__ __forceinline__ void
hgemm_body(const __half* __restrict__ Ahi, const __half* __restrict__ Alo,
           const __half* __restrict__ Bhi, const __half* __restrict__ Blo,
           const float* __restrict__ bias,
           float* __restrict__ Cf, __half* __restrict__ Chi, __half* __restrict__ Clo,
           int M, int N, int K, char* smem)
{
    constexpr int PLANE   = 8192;                    // 128 rows * 64B
    constexpr int NPLANES = (NPROD == 3) ? 4 : 3;
    constexpr int STAGE   = NPLANES * PLANE;
    const uint32_t sbase  = smem_u32(smem);

    const int bm = blockIdx.y * 128;
    const int bn = blockIdx.x * 128;
    const int t    = threadIdx.x;
    const int lane = t & 31;
    const int wid  = t >> 5;
    const int widM = wid & 1;
    const int widN = wid >> 1;
    const int g  = lane >> 2;
    const int qq = lane & 3;
    const int l7   = lane & 7;
    const int lsel = (lane >> 3) & 1;
    const int lch  = lane >> 4;

    const int cr = t >> 2;    // 0..63
    const int cc = t & 3;     // 16B chunk in 64B row

    const __half* srcb[NPLANES];
    if (NPROD == 3) {
        srcb[0] = Ahi + (long long)bm * K;
        srcb[1] = Alo + (long long)bm * K;
        srcb[2] = Bhi + (long long)bn * K;
        srcb[3] = Blo + (long long)bn * K;
    } else {
        srcb[0] = Ahi + (long long)bm * K;
        srcb[1] = Bhi + (long long)bn * K;
        srcb[2] = Blo + (long long)bn * K;
    }

    auto issue = [&](int kt, int slot) {
        const uint32_t dstb = sbase + (uint32_t)slot * STAGE;
        const long long koff = (long long)kt * 32 + cc * 8;
#pragma unroll
        for (int i = 0; i < 2 * NPLANES; ++i) {
            const int p = i >> 1;
            const int r = (i & 1) * 64 + cr;
            CPA16(sw_addr(dstb + p * PLANE, r, cc), srcb[p] + (long long)r * K + koff);
        }
    };

    float acc[4][4][4];
#pragma unroll
    for (int i = 0; i < 4; i++)
#pragma unroll
        for (int j = 0; j < 4; j++)
#pragma unroll
            for (int r = 0; r < 4; r++) acc[i][j][r] = 0.0f;

    const int nIter = K >> 5;
    const int m0 = widM * 64;
    const int n0 = widN * 32;

    issue(0, 0); CPA_COMMIT();
    issue(1, 1); CPA_COMMIT();

    for (int it = 0; it < nIter; ++it) {
        CPA_WAIT1();
        __syncthreads();
        if (it + 2 < nIter) issue(it + 2, (it + 2) % 3);
        CPA_COMMIT();

        const uint32_t stb  = sbase + (uint32_t)(it % 3) * STAGE;
        const uint32_t pAhi = stb;
        const uint32_t pAlo = (NPROD == 3) ? stb + PLANE : 0;
        const uint32_t pBhi = stb + (NPROD == 3 ? 2 : 1) * PLANE;
        const uint32_t pBlo = stb + (NPROD == 3 ? 3 : 2) * PLANE;

#pragma unroll
        for (int kk = 0; kk < 2; ++kk) {
            const int c = 2 * kk + lch;
            uint32_t bh[4][2], bl[4][2];
#pragma unroll
            for (int np = 0; np < 2; ++np) {
                const int row = n0 + np * 16 + l7 + lsel * 8;
                uint32_t r0, r1, r2, r3;
                LDSM4(r0, r1, r2, r3, sw_addr(pBhi, row, c));
                bh[np * 2][0] = r0; bh[np * 2][1] = r2;
                bh[np * 2 + 1][0] = r1; bh[np * 2 + 1][1] = r3;
                LDSM4(r0, r1, r2, r3, sw_addr(pBlo, row, c));
                bl[np * 2][0] = r0; bl[np * 2][1] = r2;
                bl[np * 2 + 1][0] = r1; bl[np * 2 + 1][1] = r3;
            }
#pragma unroll
            for (int mt = 0; mt < 4; ++mt) {
                const int row = m0 + mt * 16 + l7 + lsel * 8;
                uint32_t ah[4], al[4];
                LDSM4(ah[0], ah[1], ah[2], ah[3], sw_addr(pAhi, row, c));
                if (NPROD == 3)
                    LDSM4(al[0], al[1], al[2], al[3], sw_addr(pAlo, row, c));
#pragma unroll
                for (int nt = 0; nt < 4; ++nt) {
                    MMA16816(acc[mt][nt], ah, bh[nt]);
                    MMA16816(acc[mt][nt], ah, bl[nt]);
                    if (NPROD == 3) MMA16816(acc[mt][nt], al, bh[nt]);
                }
            }
        }
    }

    // ---- epilogue ----
#pragma unroll
    for (int nt = 0; nt < 4; ++nt) {
        const int col = bn + n0 + nt * 8 + 2 * qq;
        float b0 = 0.f, b1 = 0.f;
        if (BIAS) { b0 = bias[col]; b1 = bias[col + 1]; }
#pragma unroll
        for (int mt = 0; mt < 4; ++mt) {
            const int row0 = bm + m0 + mt * 16 + g;
            const float v0 = acc[mt][nt][0] + b0, v1 = acc[mt][nt][1] + b1;
            const float v2 = acc[mt][nt][2] + b0, v3 = acc[mt][nt][3] + b1;
            if (OMODE == 0) {
                *(float2*)(Cf + (long long)row0 * N + col)       = make_float2(v0, v1);
                *(float2*)(Cf + (long long)(row0 + 8) * N + col) = make_float2(v2, v3);
            } else {
                __half2 h0 = __floats2half2_rn(v0, v1);
                float2 f0 = __half22float2(h0);
                __half2 l0 = __floats2half2_rn(v0 - f0.x, v1 - f0.y);
                __half2 h1 = __floats2half2_rn(v2, v3);
                float2 f1 = __half22float2(h1);
                __half2 l1 = __floats2half2_rn(v2 - f1.x, v3 - f1.y);
                *(__half2*)(Chi + (long long)row0 * N + col)       = h0;
                *(__half2*)(Clo + (long long)row0 * N + col)       = l0;
                *(__half2*)(Chi + (long long)(row0 + 8) * N + col) = h1;
                *(__half2*)(Clo + (long long)(row0 + 8) * N + col) = l1;
            }
        }
    }
}

// Generic wrapper: batch offsets via blockIdx.z
template <int OMODE, bool BIAS, int NPROD>
__global__ void __launch_bounds__(256, 2)
hgemm_kernel(const __half* __restrict__ Ahi, const __half* __restrict__ Alo,
             const __half* __restrict__ Bhi, const __half* __restrict__ Blo,
             const float* __restrict__ bias,
             float* __restrict__ Cf, __half* __restrict__ Chi, __half* __restrict__ Clo,
             int M, int N, int K,
             long long sA, long long sB, long long sC)
{
    extern __shared__ char smem[];
    const long long zo = (long long)blockIdx.z;
    hgemm_body<OMODE, BIAS, NPROD>(
        Ahi + zo * sA, (NPROD == 3) ? Alo + zo * sA : nullptr,
        Bhi + zo * sB, Blo + zo * sB,
        bias,
        (OMODE == 0) ? Cf + zo * sC : nullptr,
        (OMODE == 1) ? Chi + zo * sC : nullptr,
        (OMODE == 1) ? Clo + zo * sC : nullptr,
        M, N, K, smem);
}

// Fused q/k projection: blockIdx.z selects operand set (wave packing)
struct QKArgs {
    const __half *Ah[2], *Al[2], *Bh[2], *Bl[2];
    const float* bias[2];
    __half *Ch[2], *Cl[2];
};
__global__ void __launch_bounds__(256, 2)
hgemm_qk_kernel(QKArgs a, int M, int N, int K)
{
    extern __shared__ char smem[];
    const int z = blockIdx.z;
    hgemm_body<1, true, 3>(a.Ah[z], a.Al[z], a.Bh[z], a.Bl[z], a.bias[z],
                           nullptr, a.Ch[z], a.Cl[z], M, N, K, smem);
}

// ---------------------------------------------------------------------------
// fp32 -> hi/lo fp16 planes (elementwise, float4 granularity)
// ---------------------------------------------------------------------------
__global__ void __launch_bounds__(256)
convert_kernel(const float* __restrict__ in, __half* __restrict__ hi,
               __half* __restrict__ lo, size_t n4)
{
    size_t i = (size_t)blockIdx.x * blockDim.x + threadIdx.x;
    if (i >= n4) return;
    float4 v = ((const float4*)in)[i];
    __half2 h0 = __floats2half2_rn(v.x, v.y), h1 = __floats2half2_rn(v.z, v.w);
    float2 f0 = __half22float2(h0), f1 = __half22float2(h1);
    __half2 l0 = __floats2half2_rn(v.x - f0.x, v.y - f0.y);
    __half2 l1 = __floats2half2_rn(v.z - f1.x, v.w - f1.y);
    ((__half2*)hi)[2 * i] = h0; ((__half2*)hi)[2 * i + 1] = h1;
    ((__half2*)lo)[2 * i] = l0; ((__half2*)lo)[2 * i + 1] = l1;
}

// ---------------------------------------------------------------------------
// fp32 [R,C] -> transposed hi/lo fp16 [C,R]; batched via blockIdx.z
// ---------------------------------------------------------------------------
__global__ void __launch_bounds__(256)
transpose_convert_kernel(const float* __restrict__ in, __half* __restrict__ hi,
                         __half* __restrict__ lo, int R, int Cc,
                         long long sIn, long long sOut)
{
    __shared__ float tb[32][33];
    in += (long long)blockIdx.z * sIn;
    hi += (long long)blockIdx.z * sOut;
    lo += (long long)blockIdx.z * sOut;
    const int c0 = blockIdx.x * 32;
    const int r0 = blockIdx.y * 32;
    const int x = threadIdx.x & 31;
    const int y = threadIdx.x >> 5;
#pragma unroll
    for (int j = 0; j < 32; j += 8)
        tb[y + j][x] = in[(long long)(r0 + y + j) * Cc + c0 + x];
    __syncthreads();
#pragma unroll
    for (int j = 0; j < 32; j += 8) {
        const float v = tb[x][y + j];
        const __half h = __float2half_rn(v);
        const __half l = __float2half_rn(v - __half2float(h));
        const long long o = (long long)(c0 + y + j) * R + r0 + x;
        hi[o] = h; lo[o] = l;
    }
}

// ---------------------------------------------------------------------------
// Row softmax over 2048 cols, fp32 in -> hi/lo fp16 out.
// ---------------------------------------------------------------------------
__global__ void __launch_bounds__(256)
softmax_hilo_kernel(const float* __restrict__ in, __half* __restrict__ hi,
                    __half* __restrict__ lo, int cols)
{
    const long long row = blockIdx.x;
    const float* p = in + row * (long long)cols;
    const int t = threadIdx.x;

    float v[8];
    float vmax = -3.4e38f;
#pragma unroll
    for (int i = 0; i < 8; i++) {
        v[i] = p[t + i * 256];
        vmax = fmaxf(vmax, v[i]);
    }
    __shared__ float red[256];
    red[t] = vmax;
    __syncthreads();
#pragma unroll
    for (int s = 128; s > 0; s >>= 1) {
        if (t < s) red[t] = fmaxf(red[t], red[t + s]);
        __syncthreads();
    }
    vmax = red[0];
    __syncthreads();

    float sum = 0.0f;
#pragma unroll
    for (int i = 0; i < 8; i++) {
        v[i] = __expf(v[i] - vmax);
        sum += v[i];
    }
    red[t] = sum;
    __syncthreads();
#pragma unroll
    for (int s = 128; s > 0; s >>= 1) {
        if (t < s) red[t] += red[t + s];
        __syncthreads();
    }
    const float inv = 1.0f / red[0];
#pragma unroll
    for (int i = 0; i < 8; i++) {
        const float val = v[i] * inv;
        const __half h = __float2half_rn(val);
        const __half l = __float2half_rn(val - __half2float(h));
        hi[row * (long long)cols + t + i * 256] = h;
        lo[row * (long long)cols + t + i * 256] = l;
    }
}

// ---------------------------------------------------------------------------
extern "C" void kernel_launch(void* const* d_in, const int* in_sizes, int n_in,
                              void* d_out, int out_size)
{
    const float* query  = (const float*)d_in[0];
    const float* keys   = (const float*)d_in[1];
    const float* values = (const float*)d_in[2];
    const float* Wq = (const float*)d_in[3];
    const float* bq = (const float*)d_in[4];
    const float* Wk = (const float*)d_in[5];
    const float* bk = (const float*)d_in[6];
    const float* Wv = (const float*)d_in[7];
    const float* bv = (const float*)d_in[8];
    const float* Wd = (const float*)d_in[9];
    const float* bd = (const float*)d_in[10];
    float* out = (float*)d_out;

    __half *inq_h, *inq_l, *ink_h, *ink_l, *inv_h, *inv_l;
    __half *wq_h, *wq_l, *wk_h, *wk_l, *wv_h, *wv_l, *wd_h, *wd_l;
    __half *q_h, *q_l, *k_h, *k_l, *vt_h, *vt_l, *s_h, *s_l, *att_h, *att_l;
    float *v, *s;
    cudaGetSymbolAddress((void**)&inq_h, g_inq_h); cudaGetSymbolAddress((void**)&inq_l, g_inq_l);
    cudaGetSymbolAddress((void**)&ink_h, g_ink_h); cudaGetSymbolAddress((void**)&ink_l, g_ink_l);
    cudaGetSymbolAddress((void**)&inv_h, g_inv_h); cudaGetSymbolAddress((void**)&inv_l, g_inv_l);
    cudaGetSymbolAddress((void**)&wq_h, g_wq_h); cudaGetSymbolAddress((void**)&wq_l, g_wq_l);
    cudaGetSymbolAddress((void**)&wk_h, g_wk_h); cudaGetSymbolAddress((void**)&wk_l, g_wk_l);
    cudaGetSymbolAddress((void**)&wv_h, g_wv_h); cudaGetSymbolAddress((void**)&wv_l, g_wv_l);
    cudaGetSymbolAddress((void**)&wd_h, g_wd_h); cudaGetSymbolAddress((void**)&wd_l, g_wd_l);
    cudaGetSymbolAddress((void**)&q_h, g_q_h);   cudaGetSymbolAddress((void**)&q_l, g_q_l);
    cudaGetSymbolAddress((void**)&k_h, g_k_h);   cudaGetSymbolAddress((void**)&k_l, g_k_l);
    cudaGetSymbolAddress((void**)&vt_h, g_vt_h); cudaGetSymbolAddress((void**)&vt_l, g_vt_l);
    cudaGetSymbolAddress((void**)&s_h, g_s_h);   cudaGetSymbolAddress((void**)&s_l, g_s_l);
    cudaGetSymbolAddress((void**)&att_h, g_att_h); cudaGetSymbolAddress((void**)&att_l, g_att_l);
    cudaGetSymbolAddress((void**)&v, g_v);
    cudaGetSymbolAddress((void**)&s, g_s);

    const int smem3 = 3 * 4 * 8192;   // 98304 (NPROD=3)
    const int smem2 = 3 * 3 * 8192;   // 73728 (NPROD=2)
    cudaFuncSetAttribute(hgemm_qk_kernel,           cudaFuncAttributeMaxDynamicSharedMemorySize, smem3);
    cudaFuncSetAttribute(hgemm_kernel<0, true, 3>,  cudaFuncAttributeMaxDynamicSharedMemorySize, smem3);
    cudaFuncSetAttribute(hgemm_kernel<0, false, 3>, cudaFuncAttributeMaxDynamicSharedMemorySize, smem3);
    cudaFuncSetAttribute(hgemm_kernel<1, false, 2>, cudaFuncAttributeMaxDynamicSharedMemorySize, smem2);
    cudaFuncSetAttribute(hgemm_kernel<0, true, 2>,  cudaFuncAttributeMaxDynamicSharedMemorySize, smem2);

    const long long strideQKV = (long long)SS * DD;
    const long long strideS   = (long long)SS * SS;

    dim3 tb(256);

    // 0a) convert raw inputs -> hi/lo planes
    {
        const size_t n4 = (size_t)MM * DD / 4;
        const int gr = (int)((n4 + 255) / 256);
        convert_kernel<<<gr, tb>>>(query,  inq_h, inq_l, n4);
        convert_kernel<<<gr, tb>>>(keys,   ink_h, ink_l, n4);
        convert_kernel<<<gr, tb>>>(values, inv_h, inv_l, n4);
    }
    // 0b) transpose+convert weights -> [N,K] hi/lo
    {
        dim3 gt(DD / 32, DD / 32, 1);
        transpose_convert_kernel<<<gt, tb>>>(Wq, wq_h, wq_l, DD, DD, 0, 0);
        transpose_convert_kernel<<<gt, tb>>>(Wk, wk_h, wk_l, DD, DD, 0, 0);
        transpose_convert_kernel<<<gt, tb>>>(Wv, wv_h, wv_l, DD, DD, 0, 0);
        transpose_convert_kernel<<<gt, tb>>>(Wd, wd_h, wd_l, DD, DD, 0, 0);
    }

    // 1) projections: q,k fused (z=2) -> hi/lo planes; v -> fp32
    {
        QKArgs a;
        a.Ah[0] = inq_h; a.Al[0] = inq_l; a.Bh[0] = wq_h; a.Bl[0] = wq_l;
        a.bias[0] = bq;  a.Ch[0] = q_h;   a.Cl[0] = q_l;
        a.Ah[1] = ink_h; a.Al[1] = ink_l; a.Bh[1] = wk_h; a.Bl[1] = wk_l;
        a.bias[1] = bk;  a.Ch[1] = k_h;   a.Cl[1] = k_l;
        dim3 gqk(DD / 128, MM / 128, 2);
        hgemm_qk_kernel<<<gqk, tb, smem3>>>(a, MM, DD, DD);

        dim3 gg(DD / 128, MM / 128, 1);
        hgemm_kernel<0, true, 3><<<gg, tb, smem3>>>(inv_h, inv_l, wv_h, wv_l, bv,
                                                    v, nullptr, nullptr, MM, DD, DD, 0, 0, 0);
    }

    // 2) scores = q @ k^T per batch -> fp32 (full 3x split: precision-critical)
    {
        dim3 gg(SS / 128, SS / 128, BB);
        hgemm_kernel<0, false, 3><<<gg, tb, smem3>>>(q_h, q_l, k_h, k_l, nullptr,
                                                     s, nullptr, nullptr,
                                                     SS, SS, DD,
                                                     strideQKV, strideQKV, strideS);
    }

    // 3) softmax -> hi/lo planes
    softmax_hilo_kernel<<<BB * SS, tb>>>(s, s_h, s_l, SS);

    // 4) v^T per batch -> hi/lo [D,S]
    {
        dim3 gt(DD / 32, SS / 32, BB);
        transpose_convert_kernel<<<gt, tb>>>(v, vt_h, vt_l, SS, DD, strideQKV, strideQKV);
    }

    // 5) attended = attn @ v -> hi/lo planes (2-product split)
    {
        dim3 gg(DD / 128, SS / 128, BB);
        hgemm_kernel<1, false, 2><<<gg, tb, smem2>>>(s_h, nullptr, vt_h, vt_l, nullptr,
                                                     nullptr, att_h, att_l,
                                                     SS, DD, SS,
                                                     strideS, strideQKV, strideQKV);
    }

    // 6) out = attended @ Wd + bd -> fp32 (2-product split)
    {
        dim3 gg(DD / 128, MM / 128, 1);
        hgemm_kernel<0, true, 2><<<gg, tb, smem2>>>(att_h, nullptr, wd_h, wd_l, bd,
                                                    out, nullptr, nullptr, MM, DD, DD, 0, 0, 0);
    }
}